// round 1
// baseline (speedup 1.0000x reference)
#include <cuda_runtime.h>
#include <math.h>

#define BB   8
#define SS   2048
#define DD   768
#define HH   12
#define HDIM 64
#define MROWS (BB * SS)        // 16384
#define NQKV  (3 * DD)         // 2304

// ---- static device scratch (no allocations allowed) ----
__device__ float g_Wqkv[(size_t)DD * NQKV];        // [768][2304]  repacked QKV weights
__device__ float g_bqkv[NQKV];                      // [2304]
__device__ float g_qkv[(size_t)MROWS * NQKV];       // [16384][2304]  Q|K|V per row
__device__ float g_ctx[(size_t)MROWS * DD];         // [16384][768]   attention output (heads concat)

// ============================================================================
// Repack Wq/Wk/Wv [H,D,HD] -> g_Wqkv [D, 3*D] with column = sec*768 + h*64 + e
// ============================================================================
__global__ void repack_kernel(const float* __restrict__ Wq, const float* __restrict__ Wk,
                              const float* __restrict__ Wv, const float* __restrict__ bq,
                              const float* __restrict__ bk, const float* __restrict__ bv)
{
    int idx = blockIdx.x * blockDim.x + threadIdx.x;
    const int total = DD * NQKV;
    if (idx < total) {
        int n = idx % NQKV;
        int d = idx / NQKV;
        int sec = n / DD;
        int r = n - sec * DD;        // h*64 + e
        int h = r >> 6, e = r & 63;
        const float* W = (sec == 0) ? Wq : (sec == 1 ? Wk : Wv);
        g_Wqkv[idx] = W[((size_t)h * DD + d) * HDIM + e];
    }
    if (idx < NQKV) {
        int sec = idx / DD;
        int r = idx - sec * DD;
        const float* bb = (sec == 0) ? bq : (sec == 1 ? bk : bv);
        g_bqkv[idx] = bb[r];         // b* is [H,HD] contiguous = [768]
    }
}

// ============================================================================
// Generic 64x64-tile SGEMM + bias: C[M,N] = A[M,K] @ B[K,N] + bias[N]
// 256 threads, 4x4 per thread, K-tile = 16.
// ============================================================================
__device__ __forceinline__ void gemm_core(
    const float* __restrict__ A, const float* __restrict__ Bm,
    const float* __restrict__ bias, float* __restrict__ C, int N, int K)
{
    __shared__ float As[16][64];   // transposed: As[k][m]
    __shared__ float Bs[16][64];   // Bs[k][n]
    const int tid = threadIdx.x;
    const int tx = tid & 15, ty = tid >> 4;
    const int n0 = blockIdx.x * 64;
    const size_t m0 = (size_t)blockIdx.y * 64;
    const int ar = tid >> 2;            // 0..63 row in A tile
    const int ak = (tid & 3) << 2;      // 0,4,8,12
    const int bkr = tid >> 4;           // 0..15 row in B tile
    const int bn = (tid & 15) << 2;     // 0..60

    float acc[4][4] = {};
    for (int k0 = 0; k0 < K; k0 += 16) {
        float4 av = *(const float4*)&A[(m0 + ar) * K + k0 + ak];
        float4 bv = *(const float4*)&Bm[(size_t)(k0 + bkr) * N + n0 + bn];
        __syncthreads();
        As[ak + 0][ar] = av.x;
        As[ak + 1][ar] = av.y;
        As[ak + 2][ar] = av.z;
        As[ak + 3][ar] = av.w;
        *(float4*)&Bs[bkr][bn] = bv;
        __syncthreads();
        #pragma unroll
        for (int k = 0; k < 16; k++) {
            float4 a = *(const float4*)&As[k][ty << 2];
            float4 b = *(const float4*)&Bs[k][tx << 2];
            acc[0][0] += a.x * b.x; acc[0][1] += a.x * b.y; acc[0][2] += a.x * b.z; acc[0][3] += a.x * b.w;
            acc[1][0] += a.y * b.x; acc[1][1] += a.y * b.y; acc[1][2] += a.y * b.z; acc[1][3] += a.y * b.w;
            acc[2][0] += a.z * b.x; acc[2][1] += a.z * b.y; acc[2][2] += a.z * b.z; acc[2][3] += a.z * b.w;
            acc[3][0] += a.w * b.x; acc[3][1] += a.w * b.y; acc[3][2] += a.w * b.z; acc[3][3] += a.w * b.w;
        }
    }
    const int n = n0 + (tx << 2);
    #pragma unroll
    for (int ii = 0; ii < 4; ii++) {
        float4 o;
        o.x = acc[ii][0] + bias[n + 0];
        o.y = acc[ii][1] + bias[n + 1];
        o.z = acc[ii][2] + bias[n + 2];
        o.w = acc[ii][3] + bias[n + 3];
        *(float4*)&C[(m0 + (ty << 2) + ii) * N + n] = o;
    }
}

__global__ __launch_bounds__(256) void gemm_qkv_kernel(const float* __restrict__ x) {
    gemm_core(x, g_Wqkv, g_bqkv, g_qkv, NQKV, DD);
}

__global__ __launch_bounds__(256) void gemm_out_kernel(const float* __restrict__ Wp,
                                                       const float* __restrict__ bp,
                                                       float* __restrict__ out) {
    gemm_core(g_ctx, Wp, bp, out, DD, DD);
}

// ============================================================================
// Flash attention: one block = 64 queries of one (b,h). Online softmax.
// Q,K stored dim-major (transposed) in smem; V row-major; P staged in smem.
// Note reference scale: scores / (sqrt(64)+1e-6) -> fold 1/8.000001 into Q.
// ============================================================================
__global__ __launch_bounds__(256) void attn_kernel()
{
    const int bh = blockIdx.y;
    const int b = bh / HH, h = bh - b * HH;
    const int q0 = blockIdx.x * 64;
    const float* Qg = g_qkv + (size_t)b * SS * NQKV + (size_t)h * HDIM;
    const float* Kg = Qg + DD;
    const float* Vg = Qg + 2 * DD;

    __shared__ float Qt[64][65];   // Qt[dim][row], scaled
    __shared__ float Kt[64][65];   // Kt[dim][col]
    __shared__ float Vs[64][64];   // Vs[row][dim]
    __shared__ float Ps[64][65];   // probabilities

    const int tid = threadIdx.x;
    const int tx = tid & 15, ty = tid >> 4;
    const float scale = 1.0f / (8.0f + 1e-6f);

    // Load Q tile, scaled + transposed
    {
        const int r  = tid >> 2;
        const int c4 = (tid & 3) << 2;
        #pragma unroll
        for (int cc = 0; cc < 64; cc += 16) {
            float4 v = *(const float4*)&Qg[(size_t)(q0 + r) * NQKV + c4 + cc];
            Qt[c4 + cc + 0][r] = v.x * scale;
            Qt[c4 + cc + 1][r] = v.y * scale;
            Qt[c4 + cc + 2][r] = v.z * scale;
            Qt[c4 + cc + 3][r] = v.w * scale;
        }
    }

    float m[4], l[4], acc[4][4];
    #pragma unroll
    for (int ii = 0; ii < 4; ii++) {
        m[ii] = -1e30f; l[ii] = 0.0f;
        #pragma unroll
        for (int jj = 0; jj < 4; jj++) acc[ii][jj] = 0.0f;
    }

    for (int t = 0; t < SS; t += 64) {
        __syncthreads();   // protects Kt/Vs/Ps from previous iteration's readers
        {
            const int r  = tid >> 2;
            const int c4 = (tid & 3) << 2;
            #pragma unroll
            for (int cc = 0; cc < 64; cc += 16) {
                float4 kv = *(const float4*)&Kg[(size_t)(t + r) * NQKV + c4 + cc];
                Kt[c4 + cc + 0][r] = kv.x;
                Kt[c4 + cc + 1][r] = kv.y;
                Kt[c4 + cc + 2][r] = kv.z;
                Kt[c4 + cc + 3][r] = kv.w;
                float4 vv = *(const float4*)&Vg[(size_t)(t + r) * NQKV + c4 + cc];
                *(float4*)&Vs[r][c4 + cc] = vv;
            }
        }
        __syncthreads();

        // S = Q K^T (already scaled), 4x4 per thread
        float s[4][4];
        #pragma unroll
        for (int ii = 0; ii < 4; ii++)
            #pragma unroll
            for (int jj = 0; jj < 4; jj++) s[ii][jj] = 0.0f;

        #pragma unroll 16
        for (int k = 0; k < 64; k++) {
            float qa = Qt[k][(ty << 2) + 0], qb = Qt[k][(ty << 2) + 1],
                  qc = Qt[k][(ty << 2) + 2], qd = Qt[k][(ty << 2) + 3];
            float ka = Kt[k][(tx << 2) + 0], kb = Kt[k][(tx << 2) + 1],
                  kc = Kt[k][(tx << 2) + 2], kd = Kt[k][(tx << 2) + 3];
            s[0][0] += qa * ka; s[0][1] += qa * kb; s[0][2] += qa * kc; s[0][3] += qa * kd;
            s[1][0] += qb * ka; s[1][1] += qb * kb; s[1][2] += qb * kc; s[1][3] += qb * kd;
            s[2][0] += qc * ka; s[2][1] += qc * kb; s[2][2] += qc * kc; s[2][3] += qc * kd;
            s[3][0] += qd * ka; s[3][1] += qd * kb; s[3][2] += qd * kc; s[3][3] += qd * kd;
        }

        // Online softmax (rows owned by 16-lane groups: same ty half-warp)
        #pragma unroll
        for (int ii = 0; ii < 4; ii++) {
            float rm = fmaxf(fmaxf(s[ii][0], s[ii][1]), fmaxf(s[ii][2], s[ii][3]));
            #pragma unroll
            for (int o = 8; o >= 1; o >>= 1)
                rm = fmaxf(rm, __shfl_xor_sync(0xffffffffu, rm, o, 16));
            float mn = fmaxf(m[ii], rm);
            float corr = __expf(m[ii] - mn);
            float rs = 0.0f;
            #pragma unroll
            for (int jj = 0; jj < 4; jj++) {
                float p = __expf(s[ii][jj] - mn);
                Ps[(ty << 2) + ii][(tx << 2) + jj] = p;
                rs += p;
            }
            #pragma unroll
            for (int o = 8; o >= 1; o >>= 1)
                rs += __shfl_xor_sync(0xffffffffu, rs, o, 16);
            l[ii] = l[ii] * corr + rs;
            m[ii] = mn;
            acc[ii][0] *= corr; acc[ii][1] *= corr;
            acc[ii][2] *= corr; acc[ii][3] *= corr;
        }
        __syncthreads();

        // acc += P @ V
        #pragma unroll 16
        for (int j = 0; j < 64; j++) {
            float v0 = Vs[j][(tx << 2) + 0], v1 = Vs[j][(tx << 2) + 1],
                  v2 = Vs[j][(tx << 2) + 2], v3 = Vs[j][(tx << 2) + 3];
            #pragma unroll
            for (int ii = 0; ii < 4; ii++) {
                float p = Ps[(ty << 2) + ii][j];
                acc[ii][0] += p * v0; acc[ii][1] += p * v1;
                acc[ii][2] += p * v2; acc[ii][3] += p * v3;
            }
        }
    }

    // Normalize and write ctx [B,S,H*HD] (heads concatenated along last dim)
    #pragma unroll
    for (int ii = 0; ii < 4; ii++) {
        float inv = 1.0f / l[ii];
        int row = q0 + (ty << 2) + ii;
        float4 o;
        o.x = acc[ii][0] * inv; o.y = acc[ii][1] * inv;
        o.z = acc[ii][2] * inv; o.w = acc[ii][3] * inv;
        *(float4*)&g_ctx[((size_t)b * SS + row) * DD + h * HDIM + (tx << 2)] = o;
    }
}

// ============================================================================
extern "C" void kernel_launch(void* const* d_in, const int* in_sizes, int n_in,
                              void* d_out, int out_size)
{
    const float* x  = (const float*)d_in[0];
    const float* Wq = (const float*)d_in[1];
    const float* bq = (const float*)d_in[2];
    const float* Wk = (const float*)d_in[3];
    const float* bk = (const float*)d_in[4];
    const float* Wv = (const float*)d_in[5];
    const float* bv = (const float*)d_in[6];
    const float* Wp = (const float*)d_in[7];
    const float* bp = (const float*)d_in[8];
    float* out = (float*)d_out;

    repack_kernel<<<(DD * NQKV + 255) / 256, 256>>>(Wq, Wk, Wv, bq, bk, bv);
    gemm_qkv_kernel<<<dim3(NQKV / 64, MROWS / 64), 256>>>(x);
    attn_kernel<<<dim3(SS / 64, BB * HH), 256>>>();
    gemm_out_kernel<<<dim3(DD / 64, MROWS / 64), 256>>>(Wp, bp, out);
}

// round 3
// speedup vs baseline: 2.2421x; 2.2421x over previous
#include <cuda_runtime.h>
#include <cuda_bf16.h>
#include <math.h>
#include <stdint.h>

#define BBATCH 8
#define SEQ    2048
#define DMODEL 768
#define NHEAD  12
#define HD     64
#define MR     (BBATCH*SEQ)      // 16384
#define NQ     (3*DMODEL)        // 2304

typedef __nv_bfloat16 bf16;

// ---- static device scratch (no allocations allowed) ----
__device__ bf16  g_xh[(size_t)MR*DMODEL],  g_xl[(size_t)MR*DMODEL];
__device__ bf16  g_Wth[(size_t)NQ*DMODEL], g_Wtl[(size_t)NQ*DMODEL];   // [n][k] n-major
__device__ float g_bqkv[NQ];
__device__ bf16  g_Wpth[(size_t)DMODEL*DMODEL], g_Wptl[(size_t)DMODEL*DMODEL]; // [n][k]
__device__ bf16  g_qh[(size_t)MR*NQ],      g_ql[(size_t)MR*NQ];        // QKV split
__device__ bf16  g_ch[(size_t)MR*DMODEL],  g_cl[(size_t)MR*DMODEL];    // ctx split

__device__ __forceinline__ void splitf(float v, bf16 &h, bf16 &l){
    h = __float2bfloat16(v);
    l = __float2bfloat16(v - __bfloat162float(h));
}
__device__ __forceinline__ uint32_t pack2(bf16 a, bf16 b){
    union { bf16 v[2]; uint32_t u; } t; t.v[0]=a; t.v[1]=b; return t.u;
}
__device__ __forceinline__ void mma16816(float c[4], const uint32_t a[4],
                                         uint32_t b0, uint32_t b1){
    asm volatile("mma.sync.aligned.m16n8k16.row.col.f32.bf16.bf16.f32 "
        "{%0,%1,%2,%3},{%4,%5,%6,%7},{%8,%9},{%0,%1,%2,%3};"
        : "+f"(c[0]),"+f"(c[1]),"+f"(c[2]),"+f"(c[3])
        : "r"(a[0]),"r"(a[1]),"r"(a[2]),"r"(a[3]),"r"(b0),"r"(b1));
}

// ============================================================================
// Prep: split x into hi/lo bf16; repack weights to [n][k] hi/lo bf16.
// ============================================================================
__global__ void split_x_kernel(const float* __restrict__ x){
    size_t i = (size_t)blockIdx.x*blockDim.x + threadIdx.x;
    if (i < (size_t)MR*DMODEL) splitf(x[i], g_xh[i], g_xl[i]);
}

__global__ void prep_all_kernel(const float* __restrict__ Wq, const float* __restrict__ Wk,
                                const float* __restrict__ Wv, const float* __restrict__ bq,
                                const float* __restrict__ bk, const float* __restrict__ bv,
                                const float* __restrict__ Wp){
    int idx = blockIdx.x*blockDim.x + threadIdx.x;
    if (idx < NQ*DMODEL){
        int n = idx / DMODEL, k = idx - n*DMODEL;
        int sec = n / DMODEL;
        int r = n - sec*DMODEL;
        int h = r >> 6, e = r & 63;
        const float* W = (sec==0) ? Wq : (sec==1 ? Wk : Wv);
        splitf(W[((size_t)h*DMODEL + k)*HD + e], g_Wth[idx], g_Wtl[idx]);
    }
    if (idx < DMODEL*DMODEL){
        int n = idx / DMODEL, k = idx - n*DMODEL;
        splitf(Wp[(size_t)k*DMODEL + n], g_Wpth[idx], g_Wptl[idx]);
    }
    if (idx < NQ){
        int sec = idx / DMODEL, r = idx - sec*DMODEL;
        const float* bb = (sec==0) ? bq : (sec==1 ? bk : bv);
        g_bqkv[idx] = bb[r];
    }
}

// ============================================================================
// Split-bf16 MMA GEMM: C[M,N] = A[M,K] @ B[K,N] + bias  (B given as Bt[N][K])
// 128x128 tile, BK=32, 256 threads (8 warps, 2m x 4n), warp tile 64x32.
// ============================================================================
template<bool SPLIT_OUT>
__device__ __forceinline__ void gemm_core(
    const bf16* __restrict__ Ah, const bf16* __restrict__ Al,
    const bf16* __restrict__ Bth, const bf16* __restrict__ Btl,
    const float* __restrict__ bias, int K, int N,
    bf16* __restrict__ Ch, bf16* __restrict__ Cl, float* __restrict__ Cf)
{
    constexpr int SA = 40;                 // smem k-stride (bf16), 80B rows (16B-mult)
    __shared__ bf16 As[2][128*SA];
    __shared__ bf16 Bs[2][128*SA];
    const int tid  = threadIdx.x;
    const int lane = tid & 31, wid = tid >> 5;
    const int g = lane >> 2, t = lane & 3;
    const int wm = (wid & 1) * 64, wn = (wid >> 1) * 32;
    const size_t bm0 = (size_t)blockIdx.y * 128;
    const size_t bn0 = (size_t)blockIdx.x * 128;

    float acc[4][4][4];
    #pragma unroll
    for (int a=0;a<4;a++)
        #pragma unroll
        for (int b=0;b<4;b++)
            #pragma unroll
            for (int c=0;c<4;c++) acc[a][b][c] = 0.0f;

    const int lr = tid >> 2;               // 0..63
    const int lc = (tid & 3) << 3;         // 0,8,16,24
    uint4 pa[2][2], pb[2][2];
    #pragma unroll
    for (int i=0;i<2;i++){
        int r = lr + i*64;
        pa[0][i] = *(const uint4*)&Ah [(bm0 + r)*K + lc];
        pa[1][i] = *(const uint4*)&Al [(bm0 + r)*K + lc];
        pb[0][i] = *(const uint4*)&Bth[(bn0 + r)*K + lc];
        pb[1][i] = *(const uint4*)&Btl[(bn0 + r)*K + lc];
    }

    for (int k0 = 0; k0 < K; k0 += 32){
        __syncthreads();
        #pragma unroll
        for (int i=0;i<2;i++){
            int r = lr + i*64;
            *(uint4*)&As[0][r*SA + lc] = pa[0][i];
            *(uint4*)&As[1][r*SA + lc] = pa[1][i];
            *(uint4*)&Bs[0][r*SA + lc] = pb[0][i];
            *(uint4*)&Bs[1][r*SA + lc] = pb[1][i];
        }
        __syncthreads();
        if (k0 + 32 < K){
            #pragma unroll
            for (int i=0;i<2;i++){
                int r = lr + i*64;
                pa[0][i] = *(const uint4*)&Ah [(bm0 + r)*K + k0+32 + lc];
                pa[1][i] = *(const uint4*)&Al [(bm0 + r)*K + k0+32 + lc];
                pb[0][i] = *(const uint4*)&Bth[(bn0 + r)*K + k0+32 + lc];
                pb[1][i] = *(const uint4*)&Btl[(bn0 + r)*K + k0+32 + lc];
            }
        }
        #pragma unroll
        for (int ks = 0; ks < 32; ks += 16){
            uint32_t afh[4][4], afl[4][4];
            #pragma unroll
            for (int mt=0; mt<4; mt++){
                int row = wm + mt*16 + g;
                afh[mt][0] = *(const uint32_t*)&As[0][ row   *SA + ks     + 2*t];
                afh[mt][1] = *(const uint32_t*)&As[0][(row+8)*SA + ks     + 2*t];
                afh[mt][2] = *(const uint32_t*)&As[0][ row   *SA + ks + 8 + 2*t];
                afh[mt][3] = *(const uint32_t*)&As[0][(row+8)*SA + ks + 8 + 2*t];
                afl[mt][0] = *(const uint32_t*)&As[1][ row   *SA + ks     + 2*t];
                afl[mt][1] = *(const uint32_t*)&As[1][(row+8)*SA + ks     + 2*t];
                afl[mt][2] = *(const uint32_t*)&As[1][ row   *SA + ks + 8 + 2*t];
                afl[mt][3] = *(const uint32_t*)&As[1][(row+8)*SA + ks + 8 + 2*t];
            }
            #pragma unroll
            for (int nt=0; nt<4; nt++){
                int col = wn + nt*8 + g;
                uint32_t bh0 = *(const uint32_t*)&Bs[0][col*SA + ks     + 2*t];
                uint32_t bh1 = *(const uint32_t*)&Bs[0][col*SA + ks + 8 + 2*t];
                uint32_t bl0 = *(const uint32_t*)&Bs[1][col*SA + ks     + 2*t];
                uint32_t bl1 = *(const uint32_t*)&Bs[1][col*SA + ks + 8 + 2*t];
                #pragma unroll
                for (int mt=0; mt<4; mt++){
                    mma16816(acc[mt][nt], afh[mt], bh0, bh1);
                    mma16816(acc[mt][nt], afh[mt], bl0, bl1);
                    mma16816(acc[mt][nt], afl[mt], bh0, bh1);
                }
            }
        }
    }

    #pragma unroll
    for (int mt=0; mt<4; mt++){
        #pragma unroll
        for (int nt=0; nt<4; nt++){
            size_t n = bn0 + wn + nt*8 + 2*t;
            float b0v = bias[n], b1v = bias[n+1];
            size_t m = bm0 + wm + mt*16 + g;
            float v00 = acc[mt][nt][0] + b0v, v01 = acc[mt][nt][1] + b1v;
            float v10 = acc[mt][nt][2] + b0v, v11 = acc[mt][nt][3] + b1v;
            if (SPLIT_OUT){
                bf16 h0,l0,h1,l1;
                splitf(v00,h0,l0); splitf(v01,h1,l1);
                *(uint32_t*)&Ch[m*N + n] = pack2(h0,h1);
                *(uint32_t*)&Cl[m*N + n] = pack2(l0,l1);
                splitf(v10,h0,l0); splitf(v11,h1,l1);
                *(uint32_t*)&Ch[(m+8)*N + n] = pack2(h0,h1);
                *(uint32_t*)&Cl[(m+8)*N + n] = pack2(l0,l1);
            } else {
                float2 fa; fa.x = v00; fa.y = v01;
                float2 fb; fb.x = v10; fb.y = v11;
                *(float2*)&Cf[m*N + n]     = fa;
                *(float2*)&Cf[(m+8)*N + n] = fb;
            }
        }
    }
}

__global__ __launch_bounds__(256) void gemm_qkv_kernel(){
    gemm_core<true>(g_xh, g_xl, g_Wth, g_Wtl, g_bqkv, DMODEL, NQ, g_qh, g_ql, nullptr);
}
__global__ __launch_bounds__(256) void gemm_out_kernel(const float* __restrict__ bp,
                                                       float* __restrict__ out){
    gemm_core<false>(g_ch, g_cl, g_Wpth, g_Wptl, bp, DMODEL, DMODEL, nullptr, nullptr, out);
}

// ============================================================================
// Flash attention with split-bf16 MMA. Block = 64 queries of one (b,h).
// 128 threads (4 warps), warp owns 16 query rows x full 64 kv / 64 hd.
// S-fragment layout == PV A-fragment layout: P never leaves registers.
// ============================================================================
__global__ __launch_bounds__(128) void attn_mma(){
    extern __shared__ __align__(16) char smraw[];
    bf16* Qh  = (bf16*)smraw;            // [64][72]
    bf16* Ql  = Qh  + 64*72;
    bf16* Kh  = Ql  + 64*72;             // [64 kv][72 dim]
    bf16* Kl  = Kh  + 64*72;
    bf16* Vth = Kl  + 64*72;             // [64 e][66 kv]  transposed
    bf16* Vtl = Vth + 64*66;

    const int tid  = threadIdx.x;
    const int lane = tid & 31, wid = tid >> 5;
    const int g = lane >> 2, t = lane & 3;
    const int b = blockIdx.y / NHEAD, h = blockIdx.y % NHEAD;
    const int q0 = blockIdx.x * 64;
    const size_t rowbase = (size_t)b*SEQ*NQ + (size_t)h*HD;

    // Load Q tile (hi/lo)
    #pragma unroll
    for (int i=0;i<4;i++){
        int v = tid + i*128;
        int r = v >> 3, c = (v & 7) << 3;
        *(uint4*)&Qh[r*72 + c] = *(const uint4*)&g_qh[rowbase + (size_t)(q0+r)*NQ + c];
        *(uint4*)&Ql[r*72 + c] = *(const uint4*)&g_ql[rowbase + (size_t)(q0+r)*NQ + c];
    }

    float m0=-1e30f, m1=-1e30f, l0=0.0f, l1=0.0f;
    float o[8][4];
    #pragma unroll
    for (int e=0;e<8;e++){ o[e][0]=0; o[e][1]=0; o[e][2]=0; o[e][3]=0; }

    const int qr = wid*16 + g;
    const float sc = 1.0f / (8.0f + 1e-6f);

    for (int kv0 = 0; kv0 < SEQ; kv0 += 64){
        __syncthreads();
        #pragma unroll
        for (int i=0;i<4;i++){
            int v = tid + i*128;
            int r = v >> 3, c = (v & 7) << 3;
            size_t grow = rowbase + (size_t)(kv0+r)*NQ;
            *(uint4*)&Kh[r*72 + c] = *(const uint4*)&g_qh[grow + DMODEL + c];
            *(uint4*)&Kl[r*72 + c] = *(const uint4*)&g_ql[grow + DMODEL + c];
            uint4 vh = *(const uint4*)&g_qh[grow + 2*DMODEL + c];
            uint4 vl = *(const uint4*)&g_ql[grow + 2*DMODEL + c];
            const bf16* ph = (const bf16*)&vh;
            const bf16* pl = (const bf16*)&vl;
            #pragma unroll
            for (int j=0;j<8;j++){
                Vth[(c+j)*66 + r] = ph[j];
                Vtl[(c+j)*66 + r] = pl[j];
            }
        }
        __syncthreads();

        // S = Q K^T  (3-term split)
        float s[8][4];
        #pragma unroll
        for (int nt=0;nt<8;nt++){ s[nt][0]=0; s[nt][1]=0; s[nt][2]=0; s[nt][3]=0; }
        #pragma unroll
        for (int ks=0; ks<64; ks+=16){
            uint32_t ah[4], al[4];
            ah[0] = *(const uint32_t*)&Qh[ qr   *72 + ks     + 2*t];
            ah[1] = *(const uint32_t*)&Qh[(qr+8)*72 + ks     + 2*t];
            ah[2] = *(const uint32_t*)&Qh[ qr   *72 + ks + 8 + 2*t];
            ah[3] = *(const uint32_t*)&Qh[(qr+8)*72 + ks + 8 + 2*t];
            al[0] = *(const uint32_t*)&Ql[ qr   *72 + ks     + 2*t];
            al[1] = *(const uint32_t*)&Ql[(qr+8)*72 + ks     + 2*t];
            al[2] = *(const uint32_t*)&Ql[ qr   *72 + ks + 8 + 2*t];
            al[3] = *(const uint32_t*)&Ql[(qr+8)*72 + ks + 8 + 2*t];
            #pragma unroll
            for (int nt=0; nt<8; nt++){
                uint32_t bh0 = *(const uint32_t*)&Kh[(nt*8+g)*72 + ks     + 2*t];
                uint32_t bh1 = *(const uint32_t*)&Kh[(nt*8+g)*72 + ks + 8 + 2*t];
                uint32_t bl0 = *(const uint32_t*)&Kl[(nt*8+g)*72 + ks     + 2*t];
                uint32_t bl1 = *(const uint32_t*)&Kl[(nt*8+g)*72 + ks + 8 + 2*t];
                mma16816(s[nt], ah, bh0, bh1);
                mma16816(s[nt], ah, bl0, bl1);
                mma16816(s[nt], al, bh0, bh1);
            }
        }

        // Online softmax (rows qr, qr+8)
        float rm0 = -1e30f, rm1 = -1e30f;
        #pragma unroll
        for (int nt=0;nt<8;nt++){
            s[nt][0]*=sc; s[nt][1]*=sc; s[nt][2]*=sc; s[nt][3]*=sc;
            rm0 = fmaxf(rm0, fmaxf(s[nt][0], s[nt][1]));
            rm1 = fmaxf(rm1, fmaxf(s[nt][2], s[nt][3]));
        }
        rm0 = fmaxf(rm0, __shfl_xor_sync(0xffffffffu, rm0, 1));
        rm0 = fmaxf(rm0, __shfl_xor_sync(0xffffffffu, rm0, 2));
        rm1 = fmaxf(rm1, __shfl_xor_sync(0xffffffffu, rm1, 1));
        rm1 = fmaxf(rm1, __shfl_xor_sync(0xffffffffu, rm1, 2));
        float mn0 = fmaxf(m0, rm0), mn1 = fmaxf(m1, rm1);
        float cr0 = __expf(m0 - mn0), cr1 = __expf(m1 - mn1);
        m0 = mn0; m1 = mn1;

        float rs0 = 0.0f, rs1 = 0.0f;
        uint32_t ph01[8], ph23[8], pl01[8], pl23[8];
        #pragma unroll
        for (int nt=0;nt<8;nt++){
            float p0 = __expf(s[nt][0]-mn0), p1 = __expf(s[nt][1]-mn0);
            float p2 = __expf(s[nt][2]-mn1), p3 = __expf(s[nt][3]-mn1);
            rs0 += p0+p1; rs1 += p2+p3;
            bf16 a,bb,c,d;
            splitf(p0,a,bb); splitf(p1,c,d);
            ph01[nt] = pack2(a,c); pl01[nt] = pack2(bb,d);
            splitf(p2,a,bb); splitf(p3,c,d);
            ph23[nt] = pack2(a,c); pl23[nt] = pack2(bb,d);
        }
        rs0 += __shfl_xor_sync(0xffffffffu, rs0, 1);
        rs0 += __shfl_xor_sync(0xffffffffu, rs0, 2);
        rs1 += __shfl_xor_sync(0xffffffffu, rs1, 1);
        rs1 += __shfl_xor_sync(0xffffffffu, rs1, 2);
        l0 = l0*cr0 + rs0; l1 = l1*cr1 + rs1;
        #pragma unroll
        for (int e=0;e<8;e++){ o[e][0]*=cr0; o[e][1]*=cr0; o[e][2]*=cr1; o[e][3]*=cr1; }

        // O += P @ V   (P straight from registers)
        #pragma unroll
        for (int j2=0; j2<4; j2++){
            uint32_t ah[4] = {ph01[2*j2], ph23[2*j2], ph01[2*j2+1], ph23[2*j2+1]};
            uint32_t al[4] = {pl01[2*j2], pl23[2*j2], pl01[2*j2+1], pl23[2*j2+1]};
            #pragma unroll
            for (int et=0; et<8; et++){
                uint32_t bh0 = *(const uint32_t*)&Vth[(et*8+g)*66 + j2*16     + 2*t];
                uint32_t bh1 = *(const uint32_t*)&Vth[(et*8+g)*66 + j2*16 + 8 + 2*t];
                uint32_t bl0 = *(const uint32_t*)&Vtl[(et*8+g)*66 + j2*16     + 2*t];
                uint32_t bl1 = *(const uint32_t*)&Vtl[(et*8+g)*66 + j2*16 + 8 + 2*t];
                mma16816(o[et], ah, bh0, bh1);
                mma16816(o[et], ah, bl0, bl1);
                mma16816(o[et], al, bh0, bh1);
            }
        }
    }

    // Normalize, split, write ctx hi/lo
    float i0 = 1.0f/l0, i1 = 1.0f/l1;
    size_t row = (size_t)b*SEQ + q0 + wid*16 + g;
    #pragma unroll
    for (int et=0; et<8; et++){
        int n = h*HD + et*8 + 2*t;
        float v00 = o[et][0]*i0, v01 = o[et][1]*i0;
        float v10 = o[et][2]*i1, v11 = o[et][3]*i1;
        bf16 a,bb,c,d;
        splitf(v00,a,bb); splitf(v01,c,d);
        *(uint32_t*)&g_ch[row*DMODEL + n] = pack2(a,c);
        *(uint32_t*)&g_cl[row*DMODEL + n] = pack2(bb,d);
        splitf(v10,a,bb); splitf(v11,c,d);
        *(uint32_t*)&g_ch[(row+8)*DMODEL + n] = pack2(a,c);
        *(uint32_t*)&g_cl[(row+8)*DMODEL + n] = pack2(bb,d);
    }
}

// ============================================================================
extern "C" void kernel_launch(void* const* d_in, const int* in_sizes, int n_in,
                              void* d_out, int out_size)
{
    const float* x  = (const float*)d_in[0];
    const float* Wq = (const float*)d_in[1];
    const float* bq = (const float*)d_in[2];
    const float* Wk = (const float*)d_in[3];
    const float* bk = (const float*)d_in[4];
    const float* Wv = (const float*)d_in[5];
    const float* bv = (const float*)d_in[6];
    const float* Wp = (const float*)d_in[7];
    const float* bp = (const float*)d_in[8];
    float* out = (float*)d_out;

    split_x_kernel<<<((size_t)MR*DMODEL + 255)/256, 256>>>(x);
    prep_all_kernel<<<(NQ*DMODEL + 255)/256, 256>>>(Wq, Wk, Wv, bq, bk, bv, Wp);
    gemm_qkv_kernel<<<dim3(NQ/128, MR/128), 256>>>();

    const int attn_smem = (4*64*72 + 2*64*66) * (int)sizeof(bf16);  // 53760 B
    cudaFuncSetAttribute(attn_mma, cudaFuncAttributeMaxDynamicSharedMemorySize, attn_smem);
    attn_mma<<<dim3(SEQ/64, BBATCH*NHEAD), 128, attn_smem>>>();

    gemm_out_kernel<<<dim3(DMODEL/128, MR/128), 256>>>(bp, out);
}

// round 5
// speedup vs baseline: 2.9367x; 1.3098x over previous
#include <cuda_runtime.h>
#include <cuda_bf16.h>
#include <math.h>
#include <stdint.h>

#define BBATCH 8
#define SEQ    2048
#define DMODEL 768
#define NHEAD  12
#define HD     64
#define MR     (BBATCH*SEQ)      // 16384
#define NQ     (3*DMODEL)        // 2304

typedef __nv_bfloat16 bf16;

// ---- static device scratch (no allocations allowed) ----
__device__ bf16  g_xh[(size_t)MR*DMODEL],  g_xl[(size_t)MR*DMODEL];
__device__ bf16  g_Wth[(size_t)NQ*DMODEL], g_Wtl[(size_t)NQ*DMODEL];   // [n][k] n-major
__device__ float g_bqkv[NQ];
__device__ bf16  g_Wpth[(size_t)DMODEL*DMODEL], g_Wptl[(size_t)DMODEL*DMODEL]; // [n][k]
__device__ bf16  g_qh[(size_t)MR*NQ],      g_ql[(size_t)MR*NQ];        // QKV split
__device__ bf16  g_ch[(size_t)MR*DMODEL],  g_cl[(size_t)MR*DMODEL];    // ctx split

__device__ __forceinline__ void splitf(float v, bf16 &h, bf16 &l){
    h = __float2bfloat16(v);
    l = __float2bfloat16(v - __bfloat162float(h));
}
__device__ __forceinline__ uint32_t pack2(bf16 a, bf16 b){
    union { bf16 v[2]; uint32_t u; } t; t.v[0]=a; t.v[1]=b; return t.u;
}
__device__ __forceinline__ void mma16816(float c[4], const uint32_t a[4],
                                         uint32_t b0, uint32_t b1){
    asm volatile("mma.sync.aligned.m16n8k16.row.col.f32.bf16.bf16.f32 "
        "{%0,%1,%2,%3},{%4,%5,%6,%7},{%8,%9},{%0,%1,%2,%3};"
        : "+f"(c[0]),"+f"(c[1]),"+f"(c[2]),"+f"(c[3])
        : "r"(a[0]),"r"(a[1]),"r"(a[2]),"r"(a[3]),"r"(b0),"r"(b1));
}
__device__ __forceinline__ uint32_t smem_u32(const void* p){
    uint32_t r;
    asm("{ .reg .u64 t; cvta.to.shared.u64 t, %1; cvt.u32.u64 %0, t; }" : "=r"(r) : "l"(p));
    return r;
}
#define LDSM4(r0,r1,r2,r3,a) \
    asm volatile("ldmatrix.sync.aligned.m8n8.x4.shared.b16 {%0,%1,%2,%3}, [%4];" \
        : "=r"(r0),"=r"(r1),"=r"(r2),"=r"(r3) : "r"(a))
#define LDSM4T(r0,r1,r2,r3,a) \
    asm volatile("ldmatrix.sync.aligned.m8n8.x4.trans.shared.b16 {%0,%1,%2,%3}, [%4];" \
        : "=r"(r0),"=r"(r1),"=r"(r2),"=r"(r3) : "r"(a))

// ============================================================================
// Prep: split x into hi/lo bf16; repack weights to [n][k] hi/lo bf16.
// ============================================================================
__global__ void split_x_kernel(const float* __restrict__ x){
    size_t i = (size_t)blockIdx.x*blockDim.x + threadIdx.x;
    if (i < (size_t)MR*DMODEL) splitf(x[i], g_xh[i], g_xl[i]);
}

__global__ void prep_all_kernel(const float* __restrict__ Wq, const float* __restrict__ Wk,
                                const float* __restrict__ Wv, const float* __restrict__ bq,
                                const float* __restrict__ bk, const float* __restrict__ bv,
                                const float* __restrict__ Wp){
    int idx = blockIdx.x*blockDim.x + threadIdx.x;
    if (idx < NQ*DMODEL){
        int n = idx / DMODEL, k = idx - n*DMODEL;
        int sec = n / DMODEL;
        int r = n - sec*DMODEL;
        int h = r >> 6, e = r & 63;
        const float* W = (sec==0) ? Wq : (sec==1 ? Wk : Wv);
        splitf(W[((size_t)h*DMODEL + k)*HD + e], g_Wth[idx], g_Wtl[idx]);
    }
    if (idx < DMODEL*DMODEL){
        int n = idx / DMODEL, k = idx - n*DMODEL;
        splitf(Wp[(size_t)k*DMODEL + n], g_Wpth[idx], g_Wptl[idx]);
    }
    if (idx < NQ){
        int sec = idx / DMODEL, r = idx - sec*DMODEL;
        const float* bb = (sec==0) ? bq : (sec==1 ? bk : bv);
        g_bqkv[idx] = bb[r];
    }
}

// ============================================================================
// Split-bf16 MMA GEMM (proven R3 version): C = A @ Bt^T + bias.
// 128x128 tile, BK=32, 256 threads (8 warps, 2m x 4n), warp tile 64x32.
// ============================================================================
template<bool SPLIT_OUT>
__device__ __forceinline__ void gemm_core(
    const bf16* __restrict__ Ah, const bf16* __restrict__ Al,
    const bf16* __restrict__ Bth, const bf16* __restrict__ Btl,
    const float* __restrict__ bias, int K, int N,
    bf16* __restrict__ Ch, bf16* __restrict__ Cl, float* __restrict__ Cf)
{
    constexpr int SA = 40;
    __shared__ bf16 As[2][128*SA];
    __shared__ bf16 Bs[2][128*SA];
    const int tid  = threadIdx.x;
    const int lane = tid & 31, wid = tid >> 5;
    const int g = lane >> 2, t = lane & 3;
    const int wm = (wid & 1) * 64, wn = (wid >> 1) * 32;
    const size_t bm0 = (size_t)blockIdx.y * 128;
    const size_t bn0 = (size_t)blockIdx.x * 128;

    float acc[4][4][4];
    #pragma unroll
    for (int a=0;a<4;a++)
        #pragma unroll
        for (int b=0;b<4;b++)
            #pragma unroll
            for (int c=0;c<4;c++) acc[a][b][c] = 0.0f;

    const int lr = tid >> 2;
    const int lc = (tid & 3) << 3;
    uint4 pa[2][2], pb[2][2];
    #pragma unroll
    for (int i=0;i<2;i++){
        int r = lr + i*64;
        pa[0][i] = *(const uint4*)&Ah [(bm0 + r)*K + lc];
        pa[1][i] = *(const uint4*)&Al [(bm0 + r)*K + lc];
        pb[0][i] = *(const uint4*)&Bth[(bn0 + r)*K + lc];
        pb[1][i] = *(const uint4*)&Btl[(bn0 + r)*K + lc];
    }

    for (int k0 = 0; k0 < K; k0 += 32){
        __syncthreads();
        #pragma unroll
        for (int i=0;i<2;i++){
            int r = lr + i*64;
            *(uint4*)&As[0][r*SA + lc] = pa[0][i];
            *(uint4*)&As[1][r*SA + lc] = pa[1][i];
            *(uint4*)&Bs[0][r*SA + lc] = pb[0][i];
            *(uint4*)&Bs[1][r*SA + lc] = pb[1][i];
        }
        __syncthreads();
        if (k0 + 32 < K){
            #pragma unroll
            for (int i=0;i<2;i++){
                int r = lr + i*64;
                pa[0][i] = *(const uint4*)&Ah [(bm0 + r)*K + k0+32 + lc];
                pa[1][i] = *(const uint4*)&Al [(bm0 + r)*K + k0+32 + lc];
                pb[0][i] = *(const uint4*)&Bth[(bn0 + r)*K + k0+32 + lc];
                pb[1][i] = *(const uint4*)&Btl[(bn0 + r)*K + k0+32 + lc];
            }
        }
        #pragma unroll
        for (int ks = 0; ks < 32; ks += 16){
            uint32_t afh[4][4], afl[4][4];
            #pragma unroll
            for (int mt=0; mt<4; mt++){
                int row = wm + mt*16 + g;
                afh[mt][0] = *(const uint32_t*)&As[0][ row   *SA + ks     + 2*t];
                afh[mt][1] = *(const uint32_t*)&As[0][(row+8)*SA + ks     + 2*t];
                afh[mt][2] = *(const uint32_t*)&As[0][ row   *SA + ks + 8 + 2*t];
                afh[mt][3] = *(const uint32_t*)&As[0][(row+8)*SA + ks + 8 + 2*t];
                afl[mt][0] = *(const uint32_t*)&As[1][ row   *SA + ks     + 2*t];
                afl[mt][1] = *(const uint32_t*)&As[1][(row+8)*SA + ks     + 2*t];
                afl[mt][2] = *(const uint32_t*)&As[1][ row   *SA + ks + 8 + 2*t];
                afl[mt][3] = *(const uint32_t*)&As[1][(row+8)*SA + ks + 8 + 2*t];
            }
            #pragma unroll
            for (int nt=0; nt<4; nt++){
                int col = wn + nt*8 + g;
                uint32_t bh0 = *(const uint32_t*)&Bs[0][col*SA + ks     + 2*t];
                uint32_t bh1 = *(const uint32_t*)&Bs[0][col*SA + ks + 8 + 2*t];
                uint32_t bl0 = *(const uint32_t*)&Bs[1][col*SA + ks     + 2*t];
                uint32_t bl1 = *(const uint32_t*)&Bs[1][col*SA + ks + 8 + 2*t];
                #pragma unroll
                for (int mt=0; mt<4; mt++){
                    mma16816(acc[mt][nt], afh[mt], bh0, bh1);
                    mma16816(acc[mt][nt], afh[mt], bl0, bl1);
                    mma16816(acc[mt][nt], afl[mt], bh0, bh1);
                }
            }
        }
    }

    #pragma unroll
    for (int mt=0; mt<4; mt++){
        #pragma unroll
        for (int nt=0; nt<4; nt++){
            size_t n = bn0 + wn + nt*8 + 2*t;
            float b0v = bias[n], b1v = bias[n+1];
            size_t m = bm0 + wm + mt*16 + g;
            float v00 = acc[mt][nt][0] + b0v, v01 = acc[mt][nt][1] + b1v;
            float v10 = acc[mt][nt][2] + b0v, v11 = acc[mt][nt][3] + b1v;
            if (SPLIT_OUT){
                bf16 h0,l0,h1,l1;
                splitf(v00,h0,l0); splitf(v01,h1,l1);
                *(uint32_t*)&Ch[m*N + n] = pack2(h0,h1);
                *(uint32_t*)&Cl[m*N + n] = pack2(l0,l1);
                splitf(v10,h0,l0); splitf(v11,h1,l1);
                *(uint32_t*)&Ch[(m+8)*N + n] = pack2(h0,h1);
                *(uint32_t*)&Cl[(m+8)*N + n] = pack2(l0,l1);
            } else {
                float2 fa; fa.x = v00; fa.y = v01;
                float2 fb; fb.x = v10; fb.y = v11;
                *(float2*)&Cf[m*N + n]     = fa;
                *(float2*)&Cf[(m+8)*N + n] = fb;
            }
        }
    }
}

__global__ __launch_bounds__(256) void gemm_qkv_kernel(){
    gemm_core<true>(g_xh, g_xl, g_Wth, g_Wtl, g_bqkv, DMODEL, NQ, g_qh, g_ql, nullptr);
}
__global__ __launch_bounds__(256) void gemm_out_kernel(const float* __restrict__ bp,
                                                       float* __restrict__ out){
    gemm_core<false>(g_ch, g_cl, g_Wpth, g_Wptl, bp, DMODEL, DMODEL, nullptr, nullptr, out);
}

// ============================================================================
// Flash attention v2: 128-q-row blocks, 4 warps x 32 rows (2 m-tiles/warp),
// ldmatrix fragment loads, V row-major + ldmatrix.trans (no scalar transpose).
// ============================================================================
__global__ __launch_bounds__(128) void attn_mma(){
    extern __shared__ __align__(16) char smraw[];
    bf16* Qh = (bf16*)smraw;           // [128][72]
    bf16* Ql = Qh + 128*72;
    bf16* Kh = Ql + 128*72;            // [64 kv][72 dim]
    bf16* Kl = Kh + 64*72;
    bf16* Vh = Kl + 64*72;             // [64 kv][72 e]  row-major
    bf16* Vl = Vh + 64*72;

    const int tid  = threadIdx.x;
    const int lane = tid & 31, wid = tid >> 5;
    const int g = lane >> 2, t = lane & 3;
    const int b = blockIdx.y / NHEAD, h = blockIdx.y % NHEAD;
    const int q0 = blockIdx.x * 128;
    const size_t rowbase = (size_t)b*SEQ*NQ + (size_t)h*HD;

    const uint32_t aQh = smem_u32(Qh), aQl = smem_u32(Ql);
    const uint32_t aKh = smem_u32(Kh), aKl = smem_u32(Kl);
    const uint32_t aVh = smem_u32(Vh), aVl = smem_u32(Vl);

    // Load Q tile (128 rows), vectorized
    #pragma unroll
    for (int i=0;i<8;i++){
        int v = tid + i*128;
        int r = v >> 3, c = (v & 7) << 3;
        *(uint4*)&Qh[r*72 + c] = *(const uint4*)&g_qh[rowbase + (size_t)(q0+r)*NQ + c];
        *(uint4*)&Ql[r*72 + c] = *(const uint4*)&g_ql[rowbase + (size_t)(q0+r)*NQ + c];
    }

    // ldmatrix per-lane offsets (bf16 element units)
    const int offA = (lane & 15)*72 + (lane >> 4)*8;                        // A frag 16x16
    const int offB = ((lane & 7) + (lane >> 4)*8)*72 + ((lane >> 3) & 1)*8; // B frag (n-major)
    const int offV = ((lane & 7) + ((lane >> 3) & 1)*8)*72 + (lane >> 4)*8; // trans frag

    float m[2][2], l[2][2], o[2][8][4];
    #pragma unroll
    for (int mt=0;mt<2;mt++){
        m[mt][0]=-1e30f; m[mt][1]=-1e30f; l[mt][0]=0.0f; l[mt][1]=0.0f;
        #pragma unroll
        for (int e=0;e<8;e++){ o[mt][e][0]=0; o[mt][e][1]=0; o[mt][e][2]=0; o[mt][e][3]=0; }
    }
    const float sc = 1.0f / (8.0f + 1e-6f);

    for (int kv0 = 0; kv0 < SEQ; kv0 += 64){
        __syncthreads();
        // Load K, V (64 rows each), all vectorized, V row-major
        #pragma unroll
        for (int i=0;i<4;i++){
            int v = tid + i*128;
            int r = v >> 3, c = (v & 7) << 3;
            size_t grow = rowbase + (size_t)(kv0+r)*NQ;
            *(uint4*)&Kh[r*72 + c] = *(const uint4*)&g_qh[grow + DMODEL + c];
            *(uint4*)&Kl[r*72 + c] = *(const uint4*)&g_ql[grow + DMODEL + c];
            *(uint4*)&Vh[r*72 + c] = *(const uint4*)&g_qh[grow + 2*DMODEL + c];
            *(uint4*)&Vl[r*72 + c] = *(const uint4*)&g_ql[grow + 2*DMODEL + c];
        }
        __syncthreads();

        // ---- S = Q K^T (3-term split), 2 m-tiles per warp ----
        float s[2][8][4];
        #pragma unroll
        for (int mt=0;mt<2;mt++)
            #pragma unroll
            for (int nt=0;nt<8;nt++){ s[mt][nt][0]=0; s[mt][nt][1]=0; s[mt][nt][2]=0; s[mt][nt][3]=0; }

        #pragma unroll
        for (int ks=0; ks<64; ks+=16){
            uint32_t ah[2][4], al[2][4];
            #pragma unroll
            for (int mt=0; mt<2; mt++){
                uint32_t adr = aQh + 2*((wid*32 + mt*16)*72 + ks + offA);
                LDSM4(ah[mt][0], ah[mt][1], ah[mt][2], ah[mt][3], adr);
                adr = aQl + 2*((wid*32 + mt*16)*72 + ks + offA);
                LDSM4(al[mt][0], al[mt][1], al[mt][2], al[mt][3], adr);
            }
            #pragma unroll
            for (int np=0; np<4; np++){
                uint32_t kh0,kh1,kh2,kh3, kl0,kl1,kl2,kl3;
                uint32_t adr = aKh + 2*((np*16)*72 + ks + offB);
                LDSM4(kh0,kh1,kh2,kh3, adr);
                adr = aKl + 2*((np*16)*72 + ks + offB);
                LDSM4(kl0,kl1,kl2,kl3, adr);
                #pragma unroll
                for (int mt=0; mt<2; mt++){
                    mma16816(s[mt][2*np  ], ah[mt], kh0, kh1);
                    mma16816(s[mt][2*np  ], ah[mt], kl0, kl1);
                    mma16816(s[mt][2*np  ], al[mt], kh0, kh1);
                    mma16816(s[mt][2*np+1], ah[mt], kh2, kh3);
                    mma16816(s[mt][2*np+1], ah[mt], kl2, kl3);
                    mma16816(s[mt][2*np+1], al[mt], kh2, kh3);
                }
            }
        }

        // ---- Online softmax per m-tile ----
        uint32_t ph01[2][8], ph23[2][8], pl01[2][8], pl23[2][8];
        #pragma unroll
        for (int mt=0; mt<2; mt++){
            float rm0 = -1e30f, rm1 = -1e30f;
            #pragma unroll
            for (int nt=0;nt<8;nt++){
                s[mt][nt][0]*=sc; s[mt][nt][1]*=sc; s[mt][nt][2]*=sc; s[mt][nt][3]*=sc;
                rm0 = fmaxf(rm0, fmaxf(s[mt][nt][0], s[mt][nt][1]));
                rm1 = fmaxf(rm1, fmaxf(s[mt][nt][2], s[mt][nt][3]));
            }
            rm0 = fmaxf(rm0, __shfl_xor_sync(0xffffffffu, rm0, 1));
            rm0 = fmaxf(rm0, __shfl_xor_sync(0xffffffffu, rm0, 2));
            rm1 = fmaxf(rm1, __shfl_xor_sync(0xffffffffu, rm1, 1));
            rm1 = fmaxf(rm1, __shfl_xor_sync(0xffffffffu, rm1, 2));
            float mn0 = fmaxf(m[mt][0], rm0), mn1 = fmaxf(m[mt][1], rm1);
            float cr0 = __expf(m[mt][0] - mn0), cr1 = __expf(m[mt][1] - mn1);
            m[mt][0] = mn0; m[mt][1] = mn1;

            float rs0 = 0.0f, rs1 = 0.0f;
            #pragma unroll
            for (int nt=0;nt<8;nt++){
                float p0 = __expf(s[mt][nt][0]-mn0), p1 = __expf(s[mt][nt][1]-mn0);
                float p2 = __expf(s[mt][nt][2]-mn1), p3 = __expf(s[mt][nt][3]-mn1);
                rs0 += p0+p1; rs1 += p2+p3;
                bf16 a,bb,c,d;
                splitf(p0,a,bb); splitf(p1,c,d);
                ph01[mt][nt] = pack2(a,c); pl01[mt][nt] = pack2(bb,d);
                splitf(p2,a,bb); splitf(p3,c,d);
                ph23[mt][nt] = pack2(a,c); pl23[mt][nt] = pack2(bb,d);
            }
            rs0 += __shfl_xor_sync(0xffffffffu, rs0, 1);
            rs0 += __shfl_xor_sync(0xffffffffu, rs0, 2);
            rs1 += __shfl_xor_sync(0xffffffffu, rs1, 1);
            rs1 += __shfl_xor_sync(0xffffffffu, rs1, 2);
            l[mt][0] = l[mt][0]*cr0 + rs0; l[mt][1] = l[mt][1]*cr1 + rs1;
            #pragma unroll
            for (int e=0;e<8;e++){
                o[mt][e][0]*=cr0; o[mt][e][1]*=cr0; o[mt][e][2]*=cr1; o[mt][e][3]*=cr1;
            }
        }

        // ---- O += P @ V ----
        #pragma unroll
        for (int j2=0; j2<4; j2++){
            uint32_t aP[2][4], aPl[2][4];
            #pragma unroll
            for (int mt=0; mt<2; mt++){
                aP [mt][0]=ph01[mt][2*j2]; aP [mt][1]=ph23[mt][2*j2];
                aP [mt][2]=ph01[mt][2*j2+1]; aP [mt][3]=ph23[mt][2*j2+1];
                aPl[mt][0]=pl01[mt][2*j2]; aPl[mt][1]=pl23[mt][2*j2];
                aPl[mt][2]=pl01[mt][2*j2+1]; aPl[mt][3]=pl23[mt][2*j2+1];
            }
            #pragma unroll
            for (int ep=0; ep<4; ep++){
                uint32_t vh0,vh1,vh2,vh3, vl0,vl1,vl2,vl3;
                uint32_t adr = aVh + 2*((j2*16)*72 + ep*16 + offV);
                LDSM4T(vh0,vh1,vh2,vh3, adr);
                adr = aVl + 2*((j2*16)*72 + ep*16 + offV);
                LDSM4T(vl0,vl1,vl2,vl3, adr);
                #pragma unroll
                for (int mt=0; mt<2; mt++){
                    mma16816(o[mt][2*ep  ], aP[mt],  vh0, vh1);
                    mma16816(o[mt][2*ep  ], aP[mt],  vl0, vl1);
                    mma16816(o[mt][2*ep  ], aPl[mt], vh0, vh1);
                    mma16816(o[mt][2*ep+1], aP[mt],  vh2, vh3);
                    mma16816(o[mt][2*ep+1], aP[mt],  vl2, vl3);
                    mma16816(o[mt][2*ep+1], aPl[mt], vh2, vh3);
                }
            }
        }
    }

    // ---- Normalize, split, write ctx hi/lo ----
    #pragma unroll
    for (int mt=0; mt<2; mt++){
        float i0 = 1.0f/l[mt][0], i1 = 1.0f/l[mt][1];
        size_t row = (size_t)b*SEQ + q0 + wid*32 + mt*16 + g;
        #pragma unroll
        for (int et=0; et<8; et++){
            int n = h*HD + et*8 + 2*t;
            float v00 = o[mt][et][0]*i0, v01 = o[mt][et][1]*i0;
            float v10 = o[mt][et][2]*i1, v11 = o[mt][et][3]*i1;
            bf16 a,bb,c,d;
            splitf(v00,a,bb); splitf(v01,c,d);
            *(uint32_t*)&g_ch[row*DMODEL + n] = pack2(a,c);
            *(uint32_t*)&g_cl[row*DMODEL + n] = pack2(bb,d);
            splitf(v10,a,bb); splitf(v11,c,d);
            *(uint32_t*)&g_ch[(row+8)*DMODEL + n] = pack2(a,c);
            *(uint32_t*)&g_cl[(row+8)*DMODEL + n] = pack2(bb,d);
        }
    }
}

// ============================================================================
extern "C" void kernel_launch(void* const* d_in, const int* in_sizes, int n_in,
                              void* d_out, int out_size)
{
    const float* x  = (const float*)d_in[0];
    const float* Wq = (const float*)d_in[1];
    const float* bq = (const float*)d_in[2];
    const float* Wk = (const float*)d_in[3];
    const float* bk = (const float*)d_in[4];
    const float* Wv = (const float*)d_in[5];
    const float* bv = (const float*)d_in[6];
    const float* Wp = (const float*)d_in[7];
    const float* bp = (const float*)d_in[8];
    float* out = (float*)d_out;

    split_x_kernel<<<((size_t)MR*DMODEL + 255)/256, 256>>>(x);
    prep_all_kernel<<<(NQ*DMODEL + 255)/256, 256>>>(Wq, Wk, Wv, bq, bk, bv, Wp);
    gemm_qkv_kernel<<<dim3(NQ/128, MR/128), 256>>>();

    const int attn_smem = (2*128*72 + 4*64*72) * (int)sizeof(bf16);  // 73728 B
    cudaFuncSetAttribute(attn_mma, cudaFuncAttributeMaxDynamicSharedMemorySize, attn_smem);
    attn_mma<<<dim3(SEQ/128, BBATCH*NHEAD), 128, attn_smem>>>();

    gemm_out_kernel<<<dim3(DMODEL/128, MR/128), 256>>>(bp, out);
}

// round 6
// speedup vs baseline: 3.1705x; 1.0796x over previous
#include <cuda_runtime.h>
#include <cuda_bf16.h>
#include <math.h>
#include <stdint.h>

#define BBATCH 8
#define SEQ    2048
#define DMODEL 768
#define NHEAD  12
#define HD     64
#define MR     (BBATCH*SEQ)      // 16384
#define NQ     (3*DMODEL)        // 2304

typedef __nv_bfloat16 bf16;

// ---- static device scratch (no allocations allowed) ----
__device__ bf16  g_xh[(size_t)MR*DMODEL],  g_xl[(size_t)MR*DMODEL];
__device__ bf16  g_Wth[(size_t)NQ*DMODEL], g_Wtl[(size_t)NQ*DMODEL];   // [n][k] n-major
__device__ float g_bqkv[NQ];
__device__ bf16  g_Wpth[(size_t)DMODEL*DMODEL], g_Wptl[(size_t)DMODEL*DMODEL]; // [n][k]
__device__ bf16  g_qh[(size_t)MR*NQ],      g_ql[(size_t)MR*NQ];        // QKV split
__device__ bf16  g_ch[(size_t)MR*DMODEL],  g_cl[(size_t)MR*DMODEL];    // ctx split

__device__ __forceinline__ void splitf(float v, bf16 &h, bf16 &l){
    h = __float2bfloat16(v);
    l = __float2bfloat16(v - __bfloat162float(h));
}
__device__ __forceinline__ uint32_t pack2(bf16 a, bf16 b){
    union { bf16 v[2]; uint32_t u; } t; t.v[0]=a; t.v[1]=b; return t.u;
}
__device__ __forceinline__ void mma16816(float c[4], const uint32_t a[4],
                                         uint32_t b0, uint32_t b1){
    asm volatile("mma.sync.aligned.m16n8k16.row.col.f32.bf16.bf16.f32 "
        "{%0,%1,%2,%3},{%4,%5,%6,%7},{%8,%9},{%0,%1,%2,%3};"
        : "+f"(c[0]),"+f"(c[1]),"+f"(c[2]),"+f"(c[3])
        : "r"(a[0]),"r"(a[1]),"r"(a[2]),"r"(a[3]),"r"(b0),"r"(b1));
}
__device__ __forceinline__ uint32_t smem_u32(const void* p){
    uint32_t r;
    asm("{ .reg .u64 t; cvta.to.shared.u64 t, %1; cvt.u32.u64 %0, t; }" : "=r"(r) : "l"(p));
    return r;
}
__device__ __forceinline__ void cp16(uint32_t dst, const void* src){
    asm volatile("cp.async.cg.shared.global [%0], [%1], 16;" :: "r"(dst), "l"(src));
}
#define CP_COMMIT()  asm volatile("cp.async.commit_group;" ::: "memory")
#define CP_WAIT(n)   asm volatile("cp.async.wait_group %0;" :: "n"(n) : "memory")
#define LDSM4(r0,r1,r2,r3,a) \
    asm volatile("ldmatrix.sync.aligned.m8n8.x4.shared.b16 {%0,%1,%2,%3}, [%4];" \
        : "=r"(r0),"=r"(r1),"=r"(r2),"=r"(r3) : "r"(a))
#define LDSM4T(r0,r1,r2,r3,a) \
    asm volatile("ldmatrix.sync.aligned.m8n8.x4.trans.shared.b16 {%0,%1,%2,%3}, [%4];" \
        : "=r"(r0),"=r"(r1),"=r"(r2),"=r"(r3) : "r"(a))

// ============================================================================
// Prep kernels
// ============================================================================
__global__ void split_x_kernel(const float* __restrict__ x){
    size_t i = (size_t)blockIdx.x*blockDim.x + threadIdx.x;
    if (i < (size_t)MR*DMODEL) splitf(x[i], g_xh[i], g_xl[i]);
}

__global__ void prep_all_kernel(const float* __restrict__ Wq, const float* __restrict__ Wk,
                                const float* __restrict__ Wv, const float* __restrict__ bq,
                                const float* __restrict__ bk, const float* __restrict__ bv,
                                const float* __restrict__ Wp){
    int idx = blockIdx.x*blockDim.x + threadIdx.x;
    if (idx < NQ*DMODEL){
        int n = idx / DMODEL, k = idx - n*DMODEL;
        int sec = n / DMODEL;
        int r = n - sec*DMODEL;
        int h = r >> 6, e = r & 63;
        const float* W = (sec==0) ? Wq : (sec==1 ? Wk : Wv);
        splitf(W[((size_t)h*DMODEL + k)*HD + e], g_Wth[idx], g_Wtl[idx]);
    }
    if (idx < DMODEL*DMODEL){
        int n = idx / DMODEL, k = idx - n*DMODEL;
        splitf(Wp[(size_t)k*DMODEL + n], g_Wpth[idx], g_Wptl[idx]);
    }
    if (idx < NQ){
        int sec = idx / DMODEL, r = idx - sec*DMODEL;
        const float* bb = (sec==0) ? bq : (sec==1 ? bk : bv);
        g_bqkv[idx] = bb[r];
    }
}

// ============================================================================
// Split-bf16 MMA GEMM with ldmatrix fragment loads.
// 128x128 tile, BK=32, 256 threads (8 warps, 2m x 4n), warp tile 64x32.
// ============================================================================
template<bool SPLIT_OUT>
__device__ __forceinline__ void gemm_core(
    const bf16* __restrict__ Ah, const bf16* __restrict__ Al,
    const bf16* __restrict__ Bth, const bf16* __restrict__ Btl,
    const float* __restrict__ bias, int K, int N,
    bf16* __restrict__ Ch, bf16* __restrict__ Cl, float* __restrict__ Cf)
{
    constexpr int SA = 40;
    __shared__ bf16 As[2][128*SA];
    __shared__ bf16 Bs[2][128*SA];
    const int tid  = threadIdx.x;
    const int lane = tid & 31, wid = tid >> 5;
    const int g = lane >> 2, t = lane & 3;
    const int wm = (wid & 1) * 64, wn = (wid >> 1) * 32;
    const size_t bm0 = (size_t)blockIdx.y * 128;
    const size_t bn0 = (size_t)blockIdx.x * 128;

    const uint32_t aAs0 = smem_u32(As[0]), aAs1 = smem_u32(As[1]);
    const uint32_t aBs0 = smem_u32(Bs[0]), aBs1 = smem_u32(Bs[1]);
    // ldmatrix lane offsets (element units)
    const int offA = (lane & 15)*SA + (lane >> 4)*8;
    const int offB = ((lane & 7) + (lane >> 4)*8)*SA + ((lane >> 3) & 1)*8;

    float acc[4][4][4];
    #pragma unroll
    for (int a=0;a<4;a++)
        #pragma unroll
        for (int b=0;b<4;b++)
            #pragma unroll
            for (int c=0;c<4;c++) acc[a][b][c] = 0.0f;

    const int lr = tid >> 2;
    const int lc = (tid & 3) << 3;
    uint4 pa[2][2], pb[2][2];
    #pragma unroll
    for (int i=0;i<2;i++){
        int r = lr + i*64;
        pa[0][i] = *(const uint4*)&Ah [(bm0 + r)*K + lc];
        pa[1][i] = *(const uint4*)&Al [(bm0 + r)*K + lc];
        pb[0][i] = *(const uint4*)&Bth[(bn0 + r)*K + lc];
        pb[1][i] = *(const uint4*)&Btl[(bn0 + r)*K + lc];
    }

    for (int k0 = 0; k0 < K; k0 += 32){
        __syncthreads();
        #pragma unroll
        for (int i=0;i<2;i++){
            int r = lr + i*64;
            *(uint4*)&As[0][r*SA + lc] = pa[0][i];
            *(uint4*)&As[1][r*SA + lc] = pa[1][i];
            *(uint4*)&Bs[0][r*SA + lc] = pb[0][i];
            *(uint4*)&Bs[1][r*SA + lc] = pb[1][i];
        }
        __syncthreads();
        if (k0 + 32 < K){
            #pragma unroll
            for (int i=0;i<2;i++){
                int r = lr + i*64;
                pa[0][i] = *(const uint4*)&Ah [(bm0 + r)*K + k0+32 + lc];
                pa[1][i] = *(const uint4*)&Al [(bm0 + r)*K + k0+32 + lc];
                pb[0][i] = *(const uint4*)&Bth[(bn0 + r)*K + k0+32 + lc];
                pb[1][i] = *(const uint4*)&Btl[(bn0 + r)*K + k0+32 + lc];
            }
        }
        #pragma unroll
        for (int ks = 0; ks < 32; ks += 16){
            uint32_t afh[4][4], afl[4][4];
            #pragma unroll
            for (int mt=0; mt<4; mt++){
                uint32_t adr = aAs0 + 2*((wm + mt*16)*SA + ks + offA);
                LDSM4(afh[mt][0], afh[mt][1], afh[mt][2], afh[mt][3], adr);
                adr = aAs1 + 2*((wm + mt*16)*SA + ks + offA);
                LDSM4(afl[mt][0], afl[mt][1], afl[mt][2], afl[mt][3], adr);
            }
            uint32_t bh[2][4], bl[2][4];
            #pragma unroll
            for (int np=0; np<2; np++){
                uint32_t adr = aBs0 + 2*((wn + np*16)*SA + ks + offB);
                LDSM4(bh[np][0], bh[np][1], bh[np][2], bh[np][3], adr);
                adr = aBs1 + 2*((wn + np*16)*SA + ks + offB);
                LDSM4(bl[np][0], bl[np][1], bl[np][2], bl[np][3], adr);
            }
            #pragma unroll
            for (int np=0; np<2; np++){
                #pragma unroll
                for (int hf=0; hf<2; hf++){
                    int nt = np*2 + hf;
                    uint32_t bh0 = bh[np][2*hf], bh1 = bh[np][2*hf+1];
                    uint32_t bl0 = bl[np][2*hf], bl1 = bl[np][2*hf+1];
                    #pragma unroll
                    for (int mt=0; mt<4; mt++){
                        mma16816(acc[mt][nt], afh[mt], bh0, bh1);
                        mma16816(acc[mt][nt], afh[mt], bl0, bl1);
                        mma16816(acc[mt][nt], afl[mt], bh0, bh1);
                    }
                }
            }
        }
    }

    #pragma unroll
    for (int mt=0; mt<4; mt++){
        #pragma unroll
        for (int nt=0; nt<4; nt++){
            size_t n = bn0 + wn + nt*8 + 2*t;
            float b0v = bias[n], b1v = bias[n+1];
            size_t m = bm0 + wm + mt*16 + g;
            float v00 = acc[mt][nt][0] + b0v, v01 = acc[mt][nt][1] + b1v;
            float v10 = acc[mt][nt][2] + b0v, v11 = acc[mt][nt][3] + b1v;
            if (SPLIT_OUT){
                bf16 h0,l0,h1,l1;
                splitf(v00,h0,l0); splitf(v01,h1,l1);
                *(uint32_t*)&Ch[m*N + n] = pack2(h0,h1);
                *(uint32_t*)&Cl[m*N + n] = pack2(l0,l1);
                splitf(v10,h0,l0); splitf(v11,h1,l1);
                *(uint32_t*)&Ch[(m+8)*N + n] = pack2(h0,h1);
                *(uint32_t*)&Cl[(m+8)*N + n] = pack2(l0,l1);
            } else {
                float2 fa; fa.x = v00; fa.y = v01;
                float2 fb; fb.x = v10; fb.y = v11;
                *(float2*)&Cf[m*N + n]     = fa;
                *(float2*)&Cf[(m+8)*N + n] = fb;
            }
        }
    }
}

__global__ __launch_bounds__(256) void gemm_qkv_kernel(){
    gemm_core<true>(g_xh, g_xl, g_Wth, g_Wtl, g_bqkv, DMODEL, NQ, g_qh, g_ql, nullptr);
}
__global__ __launch_bounds__(256) void gemm_out_kernel(const float* __restrict__ bp,
                                                       float* __restrict__ out){
    gemm_core<false>(g_ch, g_cl, g_Wpth, g_Wptl, bp, DMODEL, DMODEL, nullptr, nullptr, out);
}

// ============================================================================
// Flash attention: 128-q-row blocks, ldmatrix frags, cp.async double-buffered K/V.
// ============================================================================
#define KV_ARR   (64*72)                 // elements per array
#define KV_ARRB  (KV_ARR*2)              // bytes per array
#define KV_BUFB  (4*KV_ARRB)             // Kh,Kl,Vh,Vl per buffer
#define ATTN_SMEM (2*128*72*2 + 2*KV_BUFB)   // Q hi/lo + 2 KV buffers = 110592

__global__ __launch_bounds__(128) void attn_mma(){
    extern __shared__ __align__(16) char smraw[];
    bf16* Qh = (bf16*)smraw;               // [128][72]
    bf16* Ql = Qh + 128*72;
    const uint32_t aQh = smem_u32(Qh), aQl = smem_u32(Ql);
    const uint32_t aKV = aQh + 2*2*128*72; // KV buffers base

    const int tid  = threadIdx.x;
    const int lane = tid & 31, wid = tid >> 5;
    const int g = lane >> 2, t = lane & 3;
    const int b = blockIdx.y / NHEAD, h = blockIdx.y % NHEAD;
    const int q0 = blockIdx.x * 128;
    const size_t rowbase = (size_t)b*SEQ*NQ + (size_t)h*HD;

    // Load Q tile (128 rows)
    #pragma unroll
    for (int i=0;i<8;i++){
        int v = tid + i*128;
        int r = v >> 3, c = (v & 7) << 3;
        *(uint4*)&Qh[r*72 + c] = *(const uint4*)&g_qh[rowbase + (size_t)(q0+r)*NQ + c];
        *(uint4*)&Ql[r*72 + c] = *(const uint4*)&g_ql[rowbase + (size_t)(q0+r)*NQ + c];
    }

    // cp.async K/V tile loader
    auto issue_kv = [&](int it, int bufIdx){
        uint32_t base = aKV + bufIdx*KV_BUFB;
        #pragma unroll
        for (int i=0;i<4;i++){
            int v = tid + i*128;
            int r = v >> 3, c = (v & 7) << 3;
            size_t grow = rowbase + (size_t)(it*64 + r)*NQ;
            uint32_t doff = 2*(r*72 + c);
            cp16(base + 0*KV_ARRB + doff, &g_qh[grow +   DMODEL + c]);
            cp16(base + 1*KV_ARRB + doff, &g_ql[grow +   DMODEL + c]);
            cp16(base + 2*KV_ARRB + doff, &g_qh[grow + 2*DMODEL + c]);
            cp16(base + 3*KV_ARRB + doff, &g_ql[grow + 2*DMODEL + c]);
        }
        CP_COMMIT();
    };

    // ldmatrix per-lane offsets (element units, stride 72)
    const int offA = (lane & 15)*72 + (lane >> 4)*8;
    const int offB = ((lane & 7) + (lane >> 4)*8)*72 + ((lane >> 3) & 1)*8;
    const int offV = ((lane & 7) + ((lane >> 3) & 1)*8)*72 + (lane >> 4)*8;

    float m[2][2], l[2][2], o[2][8][4];
    #pragma unroll
    for (int mt=0;mt<2;mt++){
        m[mt][0]=-1e30f; m[mt][1]=-1e30f; l[mt][0]=0.0f; l[mt][1]=0.0f;
        #pragma unroll
        for (int e=0;e<8;e++){ o[mt][e][0]=0; o[mt][e][1]=0; o[mt][e][2]=0; o[mt][e][3]=0; }
    }
    const float sc = 1.0f / (8.0f + 1e-6f);
    const int NT = SEQ/64;

    issue_kv(0, 0);

    for (int it = 0; it < NT; it++){
        const int buf = it & 1;
        __syncthreads();                      // readers of buf^1 done
        if (it + 1 < NT){ issue_kv(it + 1, buf ^ 1); CP_WAIT(1); }
        else            { CP_WAIT(0); }
        __syncthreads();

        const uint32_t aKh = aKV + buf*KV_BUFB;
        const uint32_t aKl = aKh + KV_ARRB;
        const uint32_t aVh = aKl + KV_ARRB;
        const uint32_t aVl = aVh + KV_ARRB;

        // ---- S = Q K^T (3-term split), 2 m-tiles per warp ----
        float s[2][8][4];
        #pragma unroll
        for (int mt=0;mt<2;mt++)
            #pragma unroll
            for (int nt=0;nt<8;nt++){ s[mt][nt][0]=0; s[mt][nt][1]=0; s[mt][nt][2]=0; s[mt][nt][3]=0; }

        #pragma unroll
        for (int ks=0; ks<64; ks+=16){
            uint32_t ah[2][4], al[2][4];
            #pragma unroll
            for (int mt=0; mt<2; mt++){
                uint32_t adr = aQh + 2*((wid*32 + mt*16)*72 + ks + offA);
                LDSM4(ah[mt][0], ah[mt][1], ah[mt][2], ah[mt][3], adr);
                adr = aQl + 2*((wid*32 + mt*16)*72 + ks + offA);
                LDSM4(al[mt][0], al[mt][1], al[mt][2], al[mt][3], adr);
            }
            #pragma unroll
            for (int np=0; np<4; np++){
                uint32_t kh0,kh1,kh2,kh3, kl0,kl1,kl2,kl3;
                uint32_t adr = aKh + 2*((np*16)*72 + ks + offB);
                LDSM4(kh0,kh1,kh2,kh3, adr);
                adr = aKl + 2*((np*16)*72 + ks + offB);
                LDSM4(kl0,kl1,kl2,kl3, adr);
                #pragma unroll
                for (int mt=0; mt<2; mt++){
                    mma16816(s[mt][2*np  ], ah[mt], kh0, kh1);
                    mma16816(s[mt][2*np  ], ah[mt], kl0, kl1);
                    mma16816(s[mt][2*np  ], al[mt], kh0, kh1);
                    mma16816(s[mt][2*np+1], ah[mt], kh2, kh3);
                    mma16816(s[mt][2*np+1], ah[mt], kl2, kl3);
                    mma16816(s[mt][2*np+1], al[mt], kh2, kh3);
                }
            }
        }

        // ---- Online softmax per m-tile ----
        uint32_t ph01[2][8], ph23[2][8], pl01[2][8], pl23[2][8];
        #pragma unroll
        for (int mt=0; mt<2; mt++){
            float rm0 = -1e30f, rm1 = -1e30f;
            #pragma unroll
            for (int nt=0;nt<8;nt++){
                s[mt][nt][0]*=sc; s[mt][nt][1]*=sc; s[mt][nt][2]*=sc; s[mt][nt][3]*=sc;
                rm0 = fmaxf(rm0, fmaxf(s[mt][nt][0], s[mt][nt][1]));
                rm1 = fmaxf(rm1, fmaxf(s[mt][nt][2], s[mt][nt][3]));
            }
            rm0 = fmaxf(rm0, __shfl_xor_sync(0xffffffffu, rm0, 1));
            rm0 = fmaxf(rm0, __shfl_xor_sync(0xffffffffu, rm0, 2));
            rm1 = fmaxf(rm1, __shfl_xor_sync(0xffffffffu, rm1, 1));
            rm1 = fmaxf(rm1, __shfl_xor_sync(0xffffffffu, rm1, 2));
            float mn0 = fmaxf(m[mt][0], rm0), mn1 = fmaxf(m[mt][1], rm1);
            float cr0 = __expf(m[mt][0] - mn0), cr1 = __expf(m[mt][1] - mn1);
            m[mt][0] = mn0; m[mt][1] = mn1;

            float rs0 = 0.0f, rs1 = 0.0f;
            #pragma unroll
            for (int nt=0;nt<8;nt++){
                float p0 = __expf(s[mt][nt][0]-mn0), p1 = __expf(s[mt][nt][1]-mn0);
                float p2 = __expf(s[mt][nt][2]-mn1), p3 = __expf(s[mt][nt][3]-mn1);
                rs0 += p0+p1; rs1 += p2+p3;
                bf16 a,bb,c,d;
                splitf(p0,a,bb); splitf(p1,c,d);
                ph01[mt][nt] = pack2(a,c); pl01[mt][nt] = pack2(bb,d);
                splitf(p2,a,bb); splitf(p3,c,d);
                ph23[mt][nt] = pack2(a,c); pl23[mt][nt] = pack2(bb,d);
            }
            rs0 += __shfl_xor_sync(0xffffffffu, rs0, 1);
            rs0 += __shfl_xor_sync(0xffffffffu, rs0, 2);
            rs1 += __shfl_xor_sync(0xffffffffu, rs1, 1);
            rs1 += __shfl_xor_sync(0xffffffffu, rs1, 2);
            l[mt][0] = l[mt][0]*cr0 + rs0; l[mt][1] = l[mt][1]*cr1 + rs1;
            #pragma unroll
            for (int e=0;e<8;e++){
                o[mt][e][0]*=cr0; o[mt][e][1]*=cr0; o[mt][e][2]*=cr1; o[mt][e][3]*=cr1;
            }
        }

        // ---- O += P @ V ----
        #pragma unroll
        for (int j2=0; j2<4; j2++){
            uint32_t aP[2][4], aPl[2][4];
            #pragma unroll
            for (int mt=0; mt<2; mt++){
                aP [mt][0]=ph01[mt][2*j2];   aP [mt][1]=ph23[mt][2*j2];
                aP [mt][2]=ph01[mt][2*j2+1]; aP [mt][3]=ph23[mt][2*j2+1];
                aPl[mt][0]=pl01[mt][2*j2];   aPl[mt][1]=pl23[mt][2*j2];
                aPl[mt][2]=pl01[mt][2*j2+1]; aPl[mt][3]=pl23[mt][2*j2+1];
            }
            #pragma unroll
            for (int ep=0; ep<4; ep++){
                uint32_t vh0,vh1,vh2,vh3, vl0,vl1,vl2,vl3;
                uint32_t adr = aVh + 2*((j2*16)*72 + ep*16 + offV);
                LDSM4T(vh0,vh1,vh2,vh3, adr);
                adr = aVl + 2*((j2*16)*72 + ep*16 + offV);
                LDSM4T(vl0,vl1,vl2,vl3, adr);
                #pragma unroll
                for (int mt=0; mt<2; mt++){
                    mma16816(o[mt][2*ep  ], aP[mt],  vh0, vh1);
                    mma16816(o[mt][2*ep  ], aP[mt],  vl0, vl1);
                    mma16816(o[mt][2*ep  ], aPl[mt], vh0, vh1);
                    mma16816(o[mt][2*ep+1], aP[mt],  vh2, vh3);
                    mma16816(o[mt][2*ep+1], aP[mt],  vl2, vl3);
                    mma16816(o[mt][2*ep+1], aPl[mt], vh2, vh3);
                }
            }
        }
    }

    // ---- Normalize, split, write ctx hi/lo ----
    #pragma unroll
    for (int mt=0; mt<2; mt++){
        float i0 = 1.0f/l[mt][0], i1 = 1.0f/l[mt][1];
        size_t row = (size_t)b*SEQ + q0 + wid*32 + mt*16 + g;
        #pragma unroll
        for (int et=0; et<8; et++){
            int n = h*HD + et*8 + 2*t;
            float v00 = o[mt][et][0]*i0, v01 = o[mt][et][1]*i0;
            float v10 = o[mt][et][2]*i1, v11 = o[mt][et][3]*i1;
            bf16 a,bb,c,d;
            splitf(v00,a,bb); splitf(v01,c,d);
            *(uint32_t*)&g_ch[row*DMODEL + n] = pack2(a,c);
            *(uint32_t*)&g_cl[row*DMODEL + n] = pack2(bb,d);
            splitf(v10,a,bb); splitf(v11,c,d);
            *(uint32_t*)&g_ch[(row+8)*DMODEL + n] = pack2(a,c);
            *(uint32_t*)&g_cl[(row+8)*DMODEL + n] = pack2(bb,d);
        }
    }
}

// ============================================================================
extern "C" void kernel_launch(void* const* d_in, const int* in_sizes, int n_in,
                              void* d_out, int out_size)
{
    const float* x  = (const float*)d_in[0];
    const float* Wq = (const float*)d_in[1];
    const float* bq = (const float*)d_in[2];
    const float* Wk = (const float*)d_in[3];
    const float* bk = (const float*)d_in[4];
    const float* Wv = (const float*)d_in[5];
    const float* bv = (const float*)d_in[6];
    const float* Wp = (const float*)d_in[7];
    const float* bp = (const float*)d_in[8];
    float* out = (float*)d_out;

    split_x_kernel<<<((size_t)MR*DMODEL + 255)/256, 256>>>(x);
    prep_all_kernel<<<(NQ*DMODEL + 255)/256, 256>>>(Wq, Wk, Wv, bq, bk, bv, Wp);
    gemm_qkv_kernel<<<dim3(NQ/128, MR/128), 256>>>();

    cudaFuncSetAttribute(attn_mma, cudaFuncAttributeMaxDynamicSharedMemorySize, ATTN_SMEM);
    attn_mma<<<dim3(SEQ/128, BBATCH*NHEAD), 128, ATTN_SMEM>>>();

    gemm_out_kernel<<<dim3(DMODEL/128, MR/128), 256>>>(bp, out);
}